// round 8
// baseline (speedup 1.0000x reference)
#include <cuda_runtime.h>
#include <cuda_bf16.h>

// ---------------------------------------------------------------------------
// Problem constants
// ---------------------------------------------------------------------------
#define B_   8
#define D_   512
#define L_   4096
#define G_   2
#define Q_   8
#define C_   1024
#define DG_  256
#define N_   (B_ * L_)            // 32768 (b,l) positions
#define NBLK (N_ / 128)           // 256 row blocks

static const long long IDX_OFF  = (long long)N_ * D_;                      // 16777216
static const long long LOSS_OFF = IDX_OFF + (long long)G_ * B_ * L_ * Q_;  // 17301504

// ---------------------------------------------------------------------------
// Scratch (device globals -- no runtime allocation allowed)
// ---------------------------------------------------------------------------
__device__ float g_res [N_ * D_];        // h, then running residual (in-place)
__device__ float g_qout[N_ * D_];        // accumulated quantized output
__device__ float g_pwt [3 * D_ * D_];    // fused weights PWT[k][i][d]
__device__ float g_fb  [D_];             // fused bias
__device__ float g_c2  [Q_ * G_ * C_];   // ||code||^2
__device__ float g_lpart[Q_ * G_ * NBLK];// per-block loss partials

// ---------------------------------------------------------------------------
// packed f32x2 FMA helpers (2x fp32 FMA throughput; PTX-only on sm_103a)
// ---------------------------------------------------------------------------
typedef unsigned long long u64;

__device__ __forceinline__ u64 pack2(float lo, float hi) {
    u64 r;
    asm("mov.b64 %0, {%1, %2};" : "=l"(r)
        : "r"(__float_as_uint(lo)), "r"(__float_as_uint(hi)));
    return r;
}
__device__ __forceinline__ void unpack2(u64 v, float& lo, float& hi) {
    unsigned a, b;
    asm("mov.b64 {%0, %1}, %2;" : "=r"(a), "=r"(b) : "l"(v));
    lo = __uint_as_float(a);
    hi = __uint_as_float(b);
}
__device__ __forceinline__ void fma2(u64& d, u64 a, u64 b) {
    asm("fma.rn.f32x2 %0, %1, %2, %0;" : "+l"(d) : "l"(a), "l"(b));
}

// ---------------------------------------------------------------------------
// K0: zero qout (graph replays must be deterministic)
// ---------------------------------------------------------------------------
__global__ void k_zero() {
    const size_t stride = (size_t)gridDim.x * blockDim.x;
    const size_t total  = (size_t)N_ * D_;
    for (size_t i = (size_t)blockIdx.x * blockDim.x + threadIdx.x; i < total; i += stride)
        g_qout[i] = 0.f;
}

// ---------------------------------------------------------------------------
// K1: fuse weights  PWT[k][i][d] = sum_o pre_w[d][o] * conv_w[o][i][k]
// GEMM M=1536 (m=i*3+k), K=512 (o), N=512 (d). A[m][o] = cw[o*1536+m].
// ---------------------------------------------------------------------------
__global__ __launch_bounds__(256, 2)
void k_fuse(const float* __restrict__ cw, const float* __restrict__ pw) {
    __shared__ float As[8][132];
    __shared__ float Bs[8][132];
    const int m0 = blockIdx.x * 128;
    const int n0 = blockIdx.y * 128;
    const int tid = threadIdx.x;
    const int tx = tid & 15, ty = tid >> 4;

    float acc[8][8];
#pragma unroll
    for (int i = 0; i < 8; i++)
#pragma unroll
        for (int j = 0; j < 8; j++) acc[i][j] = 0.f;

    const int akk = tid >> 5;          // 0..7
    const int am4 = (tid & 31) << 2;   // 0..124
    const int bn  = tid >> 1;          // 0..127
    const int bkh = (tid & 1) << 2;    // 0 or 4

    for (int e0 = 0; e0 < D_; e0 += 8) {
        const float4 av = *(const float4*)&cw[(size_t)(e0 + akk) * (3 * D_) + m0 + am4];
        const float4 bv = *(const float4*)&pw[(size_t)(n0 + bn) * D_ + e0 + bkh];
        __syncthreads();
        *(float4*)&As[akk][am4] = av;
        Bs[bkh + 0][bn] = bv.x; Bs[bkh + 1][bn] = bv.y;
        Bs[bkh + 2][bn] = bv.z; Bs[bkh + 3][bn] = bv.w;
        __syncthreads();
#pragma unroll
        for (int kk = 0; kk < 8; kk++) {
            float aa[8], bb[8];
#pragma unroll
            for (int i = 0; i < 8; i++) aa[i] = As[kk][ty * 8 + i];
#pragma unroll
            for (int j = 0; j < 8; j++) bb[j] = Bs[kk][tx * 8 + j];
#pragma unroll
            for (int i = 0; i < 8; i++)
#pragma unroll
                for (int j = 0; j < 8; j++)
                    acc[i][j] = fmaf(aa[i], bb[j], acc[i][j]);
        }
    }
#pragma unroll
    for (int i = 0; i < 8; i++) {
        const int m = m0 + ty * 8 + i;
        const int ii = m / 3, k = m - ii * 3;
        float* dst = &g_pwt[((size_t)(k * D_ + ii)) * D_ + n0 + tx * 8];
#pragma unroll
        for (int j = 0; j < 8; j++) dst[j] = acc[i][j];
    }
}

// K1b: fused bias = pre_w @ conv_b + pre_b
__global__ void k_fb(const float* __restrict__ pw, const float* __restrict__ cbias,
                     const float* __restrict__ pbias) {
    const int d = blockIdx.x * blockDim.x + threadIdx.x;
    if (d < D_) {
        float s = pbias[d];
        for (int e = 0; e < D_; e++) s = fmaf(pw[(size_t)d * D_ + e], cbias[e], s);
        g_fb[d] = s;
    }
}

// K1c: code squared norms (one warp per code row)
__global__ void k_c2(const float* __restrict__ cbk) {
    const int w = (blockIdx.x * blockDim.x + threadIdx.x) >> 5;
    const int lane = threadIdx.x & 31;
    if (w < Q_ * G_ * C_) {
        const float* r = cbk + (size_t)w * DG_;
        float s = 0.f;
        for (int d = lane; d < DG_; d += 32) { const float v = r[d]; s = fmaf(v, v, s); }
#pragma unroll
        for (int o = 16; o; o >>= 1) s += __shfl_xor_sync(0xffffffffu, s, o);
        if (!lane) g_c2[w] = s;
    }
}

// ---------------------------------------------------------------------------
// K2: fused conv_enc + pre-linear  ->  h[row=(b,l)][d]  (written into g_res)
//     h[l][d] = sum_{i,k} PWT[k][i][d] * x[b][i][l+k-1] + fb[d]
// ---------------------------------------------------------------------------
__global__ __launch_bounds__(256, 2)
void k_conv(const float* __restrict__ x) {
    __shared__ float Xs[8][132];        // [kk][l-halo] (130 used)
    __shared__ float Ws[3][8][128];     // [tap][kk][d]
    __shared__ float fbs[128];
    const int r0 = blockIdx.x * 128;
    const int n0 = blockIdx.y * 128;
    const int b  = r0 / L_;
    const int l0 = r0 - b * L_;
    const int tid = threadIdx.x;
    const int tx = tid & 15, ty = tid >> 4;
    if (tid < 128) fbs[tid] = g_fb[n0 + tid];
    const float* xb = x + (size_t)b * D_ * L_;

    float acc[8][8];
#pragma unroll
    for (int i = 0; i < 8; i++)
#pragma unroll
        for (int j = 0; j < 8; j++) acc[i][j] = 0.f;

    for (int i0 = 0; i0 < D_; i0 += 8) {
        __syncthreads();
        for (int idx = tid; idx < 8 * 130; idx += 256) {
            const int kk = idx / 130, j = idx - kk * 130;
            const int lg = l0 + j - 1;
            Xs[kk][j] = (lg >= 0 && lg < L_) ? xb[(size_t)(i0 + kk) * L_ + lg] : 0.f;
        }
        for (int c = tid; c < 768; c += 256) {
            const int k = c >> 8, rem = c & 255;
            const int kk = rem >> 5, n4 = (rem & 31) << 2;
            *(float4*)&Ws[k][kk][n4] =
                *(const float4*)&g_pwt[((size_t)(k * D_ + i0 + kk)) * D_ + n0 + n4];
        }
        __syncthreads();
#pragma unroll
        for (int kk = 0; kk < 8; kk++) {
            float xv[10];
#pragma unroll
            for (int u = 0; u < 10; u++) xv[u] = Xs[kk][ty * 8 + u];
#pragma unroll
            for (int k = 0; k < 3; k++) {
                float wj[8];
#pragma unroll
                for (int j = 0; j < 8; j++) wj[j] = Ws[k][kk][tx * 8 + j];
#pragma unroll
                for (int i = 0; i < 8; i++)
#pragma unroll
                    for (int j = 0; j < 8; j++)
                        acc[i][j] = fmaf(xv[i + k], wj[j], acc[i][j]);
            }
        }
    }
#pragma unroll
    for (int i = 0; i < 8; i++) {
        float* dst = &g_res[(size_t)(r0 + ty * 8 + i) * D_ + n0 + tx * 8];
#pragma unroll
        for (int j = 0; j < 8; j++) dst[j] = acc[i][j] + fbs[tx * 8 + j];
    }
}

// ---------------------------------------------------------------------------
// K3: one residual-VQ step (quantizer q), fully fused:
//     scores GEMM (f32x2) -> running argmin -> index write ->
//     residual/qout update -> commit-loss block partial.
//     Block = 128 rows x (loop over 1024 codes in chunks of 128). grid.y = G.
// ---------------------------------------------------------------------------
__global__ __launch_bounds__(256, 2)
void k_vq(const float* __restrict__ cbks, float* __restrict__ out, int q) {
    __shared__ float Rs[8][132];
    __shared__ float Cs[8][132];
    __shared__ float c2s[128];
    __shared__ float redv[128][17];
    __shared__ int   redi[128][17];
    __shared__ int   bidx[128];
    __shared__ float lred[256];

    const int g   = blockIdx.y;
    const int r0  = blockIdx.x * 128;
    const int tid = threadIdx.x;
    const int tx  = tid & 15, ty = tid >> 4;
    const int goff = g * DG_;
    const float* cb  = cbks + (size_t)(q * G_ + g) * C_ * DG_;
    const float* c2p = g_c2 + (q * G_ + g) * C_;

    float minv[8];
    int   mini[8];
#pragma unroll
    for (int i = 0; i < 8; i++) { minv[i] = 3.4e38f; mini[i] = 0; }

    const int ml = tid >> 1;          // 0..127
    const int kh = (tid & 1) << 2;    // 0 or 4

    for (int cc0 = 0; cc0 < C_; cc0 += 128) {
        __syncthreads();                       // prev chunk done reading c2s
        if (tid < 128) c2s[tid] = c2p[cc0 + tid];

        u64 acc2[8][4];
#pragma unroll
        for (int i = 0; i < 8; i++)
#pragma unroll
            for (int j = 0; j < 4; j++) acc2[i][j] = 0ull;

        for (int k0 = 0; k0 < DG_; k0 += 8) {
            const float4 rv = *(const float4*)&g_res[(size_t)(r0 + ml) * D_ + goff + k0 + kh];
            const float4 cv = *(const float4*)&cb[(size_t)(cc0 + ml) * DG_ + k0 + kh];
            __syncthreads();
            Rs[kh + 0][ml] = rv.x; Rs[kh + 1][ml] = rv.y;
            Rs[kh + 2][ml] = rv.z; Rs[kh + 3][ml] = rv.w;
            Cs[kh + 0][ml] = cv.x; Cs[kh + 1][ml] = cv.y;
            Cs[kh + 2][ml] = cv.z; Cs[kh + 3][ml] = cv.w;
            __syncthreads();
#pragma unroll
            for (int kk = 0; kk < 8; kk++) {
                float aa[8], bb[8];
#pragma unroll
                for (int i = 0; i < 8; i++) aa[i] = Rs[kk][ty * 8 + i];
#pragma unroll
                for (int j = 0; j < 8; j++) bb[j] = Cs[kk][tx * 8 + j];
                u64 bp[4];
                bp[0] = pack2(bb[0], bb[1]); bp[1] = pack2(bb[2], bb[3]);
                bp[2] = pack2(bb[4], bb[5]); bp[3] = pack2(bb[6], bb[7]);
#pragma unroll
                for (int i = 0; i < 8; i++) {
                    const u64 ap = pack2(aa[i], aa[i]);
                    fma2(acc2[i][0], ap, bp[0]);
                    fma2(acc2[i][1], ap, bp[1]);
                    fma2(acc2[i][2], ap, bp[2]);
                    fma2(acc2[i][3], ap, bp[3]);
                }
            }
        }
        // scores + running argmin (ascending index order within thread)
#pragma unroll
        for (int j2 = 0; j2 < 4; j2++) {
#pragma unroll
            for (int i = 0; i < 8; i++) {
                float dlo, dhi;
                unpack2(acc2[i][j2], dlo, dhi);
                const int j = j2 * 2;
                const float s0 = c2s[tx * 8 + j]     - 2.f * dlo;
                const float s1 = c2s[tx * 8 + j + 1] - 2.f * dhi;
                const int idx0 = cc0 + tx * 8 + j;
                if (s0 < minv[i]) { minv[i] = s0; mini[i] = idx0; }
                if (s1 < minv[i]) { minv[i] = s1; mini[i] = idx0 + 1; }
            }
        }
    }

    // cross-thread argmin reduce (per row, across 16 tx lanes; first-index ties)
    __syncthreads();
#pragma unroll
    for (int i = 0; i < 8; i++) {
        redv[ty * 8 + i][tx] = minv[i];
        redi[ty * 8 + i][tx] = mini[i];
    }
    __syncthreads();
    if (tid < 128) {
        float bv = redv[tid][0];
        int   bi = redi[tid][0];
#pragma unroll
        for (int t = 1; t < 16; t++) {
            const float v = redv[tid][t];
            const int   w = redi[tid][t];
            if (v < bv || (v == bv && w < bi)) { bv = v; bi = w; }
        }
        bidx[tid] = bi;
        const int row = r0 + tid;
        const int bb = row / L_;
        const int ll = row - bb * L_;
        out[IDX_OFF + (size_t)(((g * B_ + bb) * L_) + ll) * Q_ + q] = (float)bi;
    }
    __syncthreads();

    // residual -= code ; qout += code ; loss partial = ||new residual||^2
    float ls = 0.f;
    {
        const int m    = tid >> 1;
        const int half = (tid & 1) * (DG_ / 2);
        const size_t base = (size_t)(r0 + m) * D_ + goff + half;
        const float* crow = cb + (size_t)bidx[m] * DG_ + half;
#pragma unroll 4
        for (int dd = 0; dd < DG_ / 2; dd += 4) {
            const float4 cvl = *(const float4*)&crow[dd];
            float4 rvl = *(float4*)&g_res[base + dd];
            float4 qvl = *(float4*)&g_qout[base + dd];
            rvl.x -= cvl.x; rvl.y -= cvl.y; rvl.z -= cvl.z; rvl.w -= cvl.w;
            qvl.x += cvl.x; qvl.y += cvl.y; qvl.z += cvl.z; qvl.w += cvl.w;
            *(float4*)&g_res[base + dd]  = rvl;
            *(float4*)&g_qout[base + dd] = qvl;
            ls = fmaf(rvl.x, rvl.x, ls); ls = fmaf(rvl.y, rvl.y, ls);
            ls = fmaf(rvl.z, rvl.z, ls); ls = fmaf(rvl.w, rvl.w, ls);
        }
    }
    lred[tid] = ls;
    __syncthreads();
#pragma unroll
    for (int s = 128; s; s >>= 1) {
        if (tid < s) lred[tid] += lred[tid + s];
        __syncthreads();
    }
    if (tid == 0) g_lpart[(q * G_ + g) * NBLK + blockIdx.x] = lred[0];
}

// ---------------------------------------------------------------------------
// K4: post linear + [b,d,l] transpose.  Out[d][l] = sum_e pw[d][e]*qout[l][e]+pb[d]
// Tile rows = d, cols = (b,l) rows -> coalesced transposed stores.
// ---------------------------------------------------------------------------
__global__ __launch_bounds__(256, 2)
void k_post(const float* __restrict__ pw, const float* __restrict__ pb,
            float* __restrict__ out) {
    __shared__ float As[8][132];   // [kk][d]
    __shared__ float Bs[8][132];   // [kk][row]
    const int r0 = blockIdx.x * 128;
    const int d0 = blockIdx.y * 128;
    const int tid = threadIdx.x;
    const int tx = tid & 15, ty = tid >> 4;
    const int ml = tid >> 1;
    const int kh = (tid & 1) << 2;

    float acc[8][8];
#pragma unroll
    for (int i = 0; i < 8; i++)
#pragma unroll
        for (int j = 0; j < 8; j++) acc[i][j] = 0.f;

    for (int e0 = 0; e0 < D_; e0 += 8) {
        const float4 av = *(const float4*)&pw[(size_t)(d0 + ml) * D_ + e0 + kh];
        const float4 bv = *(const float4*)&g_qout[(size_t)(r0 + ml) * D_ + e0 + kh];
        __syncthreads();
        As[kh + 0][ml] = av.x; As[kh + 1][ml] = av.y;
        As[kh + 2][ml] = av.z; As[kh + 3][ml] = av.w;
        Bs[kh + 0][ml] = bv.x; Bs[kh + 1][ml] = bv.y;
        Bs[kh + 2][ml] = bv.z; Bs[kh + 3][ml] = bv.w;
        __syncthreads();
#pragma unroll
        for (int kk = 0; kk < 8; kk++) {
            float aa[8], bb[8];
#pragma unroll
            for (int i = 0; i < 8; i++) aa[i] = As[kk][ty * 8 + i];
#pragma unroll
            for (int j = 0; j < 8; j++) bb[j] = Bs[kk][tx * 8 + j];
#pragma unroll
            for (int i = 0; i < 8; i++)
#pragma unroll
                for (int j = 0; j < 8; j++)
                    acc[i][j] = fmaf(aa[i], bb[j], acc[i][j]);
        }
    }
    const int b  = r0 / L_;
    const int l0 = r0 - b * L_;
#pragma unroll
    for (int i = 0; i < 8; i++) {
        const int d = d0 + ty * 8 + i;
        const float bias = pb[d];
        float* dst = &out[(size_t)b * D_ * L_ + (size_t)d * L_ + l0 + tx * 8];
        float4 v0, v1;
        v0.x = acc[i][0] + bias; v0.y = acc[i][1] + bias;
        v0.z = acc[i][2] + bias; v0.w = acc[i][3] + bias;
        v1.x = acc[i][4] + bias; v1.y = acc[i][5] + bias;
        v1.z = acc[i][6] + bias; v1.w = acc[i][7] + bias;
        *(float4*)&dst[0] = v0;
        *(float4*)&dst[4] = v1;
    }
}

// K5: deterministic loss finalize.  losses[g][q] = sum(partials)/ (B*L*DG)
__global__ void k_loss(float* __restrict__ out) {
    const int t = threadIdx.x;
    if (t < G_ * Q_) {
        const int g = t / Q_, q = t - g * Q_;
        const float* p = &g_lpart[(q * G_ + g) * NBLK];
        float s = 0.f;
        for (int b = 0; b < NBLK; b++) s += p[b];
        out[LOSS_OFF + g * Q_ + q] = s / (float)((long long)B_ * L_ * DG_);
    }
}

// ---------------------------------------------------------------------------
// Launch
// ---------------------------------------------------------------------------
extern "C" void kernel_launch(void* const* d_in, const int* in_sizes, int n_in,
                              void* d_out, int out_size) {
    (void)in_sizes; (void)n_in; (void)out_size;
    const float* x     = (const float*)d_in[0];
    const float* cew   = (const float*)d_in[1];
    const float* ceb   = (const float*)d_in[2];
    const float* pre_w = (const float*)d_in[3];
    const float* pre_b = (const float*)d_in[4];
    const float* cbk   = (const float*)d_in[5];
    const float* pow_  = (const float*)d_in[6];
    const float* pob   = (const float*)d_in[7];
    // d_in[8], d_in[9] = conv_dec_* : the reference discards the decoder conv.
    float* out = (float*)d_out;

    k_zero<<<4096, 256>>>();
    k_fuse<<<dim3(12, 4), 256>>>(cew, pre_w);
    k_fb<<<2, 256>>>(pre_w, ceb, pre_b);
    k_c2<<<(Q_ * G_ * C_ * 32 + 255) / 256, 256>>>(cbk);
    k_conv<<<dim3(NBLK, 4), 256>>>(x);
    for (int q = 0; q < Q_; q++)
        k_vq<<<dim3(NBLK, G_), 256>>>(cbk, out, q);
    k_post<<<dim3(NBLK, 4), 256>>>(pow_, pob, out);
    k_loss<<<1, 32>>>(out);
}

// round 9
// speedup vs baseline: 1.0534x; 1.0534x over previous
#include <cuda_runtime.h>
#include <cuda_bf16.h>

// ---------------------------------------------------------------------------
// Problem constants
// ---------------------------------------------------------------------------
#define B_   8
#define D_   512
#define L_   4096
#define G_   2
#define Q_   8
#define C_   1024
#define DG_  256
#define N_   (B_ * L_)            // 32768 (b,l) positions
#define NBLK (N_ / 128)           // 256 row blocks

static const long long IDX_OFF  = (long long)N_ * D_;                      // 16777216
static const long long LOSS_OFF = IDX_OFF + (long long)G_ * B_ * L_ * Q_;  // 17301504

// ---------------------------------------------------------------------------
// Scratch (device globals -- no runtime allocation allowed)
// ---------------------------------------------------------------------------
__device__ float g_res  [N_ * D_];        // h, then running residual (in-place)
__device__ float g_qout [N_ * D_];        // accumulated quantized output
__device__ float g_pwt  [3 * D_ * D_];    // fused weights PWT[k][i][d]
__device__ float g_fb   [D_];             // fused bias
__device__ float g_c2   [Q_ * G_ * C_];   // ||code||^2
__device__ float g_lpart[Q_ * G_ * NBLK]; // per-block loss partials

// ---------------------------------------------------------------------------
// packed f32x2 FMA helpers (2x fp32 FMA throughput; PTX-only on sm_103a)
// ---------------------------------------------------------------------------
typedef unsigned long long u64;

__device__ __forceinline__ u64 pack2(float lo, float hi) {
    u64 r;
    asm("mov.b64 %0, {%1, %2};" : "=l"(r)
        : "r"(__float_as_uint(lo)), "r"(__float_as_uint(hi)));
    return r;
}
__device__ __forceinline__ void unpack2(u64 v, float& lo, float& hi) {
    unsigned a, b;
    asm("mov.b64 {%0, %1}, %2;" : "=r"(a), "=r"(b) : "l"(v));
    lo = __uint_as_float(a);
    hi = __uint_as_float(b);
}
__device__ __forceinline__ void fma2(u64& d, u64 a, u64 b) {
    asm("fma.rn.f32x2 %0, %1, %2, %0;" : "+l"(d) : "l"(a), "l"(b));
}

// ---------------------------------------------------------------------------
// K1: fuse weights  PWT[k][i][d] = sum_o pre_w[d][o] * conv_w[o][i][k]
// GEMM M=1536 (m=i*3+k), K=512 (o), N=512 (d). A[m][o] = cw[o*1536+m].
// ---------------------------------------------------------------------------
__global__ __launch_bounds__(256, 2)
void k_fuse(const float* __restrict__ cw, const float* __restrict__ pw) {
    __shared__ float As[8][132];
    __shared__ float Bs[8][132];
    const int m0 = blockIdx.x * 128;
    const int n0 = blockIdx.y * 128;
    const int tid = threadIdx.x;
    const int tx = tid & 15, ty = tid >> 4;

    float acc[8][8];
#pragma unroll
    for (int i = 0; i < 8; i++)
#pragma unroll
        for (int j = 0; j < 8; j++) acc[i][j] = 0.f;

    const int akk = tid >> 5;          // 0..7
    const int am4 = (tid & 31) << 2;   // 0..124
    const int bn  = tid >> 1;          // 0..127
    const int bkh = (tid & 1) << 2;    // 0 or 4

    for (int e0 = 0; e0 < D_; e0 += 8) {
        const float4 av = *(const float4*)&cw[(size_t)(e0 + akk) * (3 * D_) + m0 + am4];
        const float4 bv = *(const float4*)&pw[(size_t)(n0 + bn) * D_ + e0 + bkh];
        __syncthreads();
        *(float4*)&As[akk][am4] = av;
        Bs[bkh + 0][bn] = bv.x; Bs[bkh + 1][bn] = bv.y;
        Bs[bkh + 2][bn] = bv.z; Bs[bkh + 3][bn] = bv.w;
        __syncthreads();
#pragma unroll
        for (int kk = 0; kk < 8; kk++) {
            float aa[8], bb[8];
#pragma unroll
            for (int i = 0; i < 8; i++) aa[i] = As[kk][ty * 8 + i];
#pragma unroll
            for (int j = 0; j < 8; j++) bb[j] = Bs[kk][tx * 8 + j];
#pragma unroll
            for (int i = 0; i < 8; i++)
#pragma unroll
                for (int j = 0; j < 8; j++)
                    acc[i][j] = fmaf(aa[i], bb[j], acc[i][j]);
        }
    }
#pragma unroll
    for (int i = 0; i < 8; i++) {
        const int m = m0 + ty * 8 + i;
        const int ii = m / 3, k = m - ii * 3;
        float* dst = &g_pwt[((size_t)(k * D_ + ii)) * D_ + n0 + tx * 8];
#pragma unroll
        for (int j = 0; j < 8; j++) dst[j] = acc[i][j];
    }
}

// K1b: fused bias = pre_w @ conv_b + pre_b
__global__ void k_fb(const float* __restrict__ pw, const float* __restrict__ cbias,
                     const float* __restrict__ pbias) {
    const int d = blockIdx.x * blockDim.x + threadIdx.x;
    if (d < D_) {
        float s = pbias[d];
        for (int e = 0; e < D_; e++) s = fmaf(pw[(size_t)d * D_ + e], cbias[e], s);
        g_fb[d] = s;
    }
}

// K1c: code squared norms (one warp per code row)
__global__ void k_c2(const float* __restrict__ cbk) {
    const int w = (blockIdx.x * blockDim.x + threadIdx.x) >> 5;
    const int lane = threadIdx.x & 31;
    if (w < Q_ * G_ * C_) {
        const float* r = cbk + (size_t)w * DG_;
        float s = 0.f;
        for (int d = lane; d < DG_; d += 32) { const float v = r[d]; s = fmaf(v, v, s); }
#pragma unroll
        for (int o = 16; o; o >>= 1) s += __shfl_xor_sync(0xffffffffu, s, o);
        if (!lane) g_c2[w] = s;
    }
}

// ---------------------------------------------------------------------------
// K2: fused conv_enc + pre-linear  ->  h[row=(b,l)][d]  (written into g_res)
//     h[l][d] = sum_{i,k} PWT[k][i][d] * x[b][i][l+k-1] + fb[d]
//     f32x2 mainloop.
// ---------------------------------------------------------------------------
__global__ __launch_bounds__(256, 2)
void k_conv(const float* __restrict__ x) {
    __shared__ float Xs[8][132];        // [kk][l-halo] (130 used)
    __shared__ float Ws[3][8][128];     // [tap][kk][d]
    __shared__ float fbs[128];
    const int r0 = blockIdx.x * 128;
    const int n0 = blockIdx.y * 128;
    const int b  = r0 / L_;
    const int l0 = r0 - b * L_;
    const int tid = threadIdx.x;
    const int tx = tid & 15, ty = tid >> 4;
    if (tid < 128) fbs[tid] = g_fb[n0 + tid];
    const float* xb = x + (size_t)b * D_ * L_;

    u64 acc2[8][4];
#pragma unroll
    for (int i = 0; i < 8; i++)
#pragma unroll
        for (int j = 0; j < 4; j++) acc2[i][j] = 0ull;

#pragma unroll 1
    for (int i0 = 0; i0 < D_; i0 += 8) {
        __syncthreads();
        for (int idx = tid; idx < 8 * 130; idx += 256) {
            const int kk = idx / 130, j = idx - kk * 130;
            const int lg = l0 + j - 1;
            Xs[kk][j] = (lg >= 0 && lg < L_) ? xb[(size_t)(i0 + kk) * L_ + lg] : 0.f;
        }
        for (int c = tid; c < 768; c += 256) {
            const int k = c >> 8, rem = c & 255;
            const int kk = rem >> 5, n4 = (rem & 31) << 2;
            *(float4*)&Ws[k][kk][n4] =
                *(const float4*)&g_pwt[((size_t)(k * D_ + i0 + kk)) * D_ + n0 + n4];
        }
        __syncthreads();
#pragma unroll
        for (int kk = 0; kk < 8; kk++) {
            u64 xp[10];
#pragma unroll
            for (int u = 0; u < 10; u++) {
                const float v = Xs[kk][ty * 8 + u];
                xp[u] = pack2(v, v);
            }
#pragma unroll
            for (int k = 0; k < 3; k++) {
                const float4 w0 = *(const float4*)&Ws[k][kk][tx * 8];
                const float4 w1 = *(const float4*)&Ws[k][kk][tx * 8 + 4];
                const u64 bp0 = pack2(w0.x, w0.y), bp1 = pack2(w0.z, w0.w);
                const u64 bp2 = pack2(w1.x, w1.y), bp3 = pack2(w1.z, w1.w);
#pragma unroll
                for (int i = 0; i < 8; i++) {
                    fma2(acc2[i][0], xp[i + k], bp0);
                    fma2(acc2[i][1], xp[i + k], bp1);
                    fma2(acc2[i][2], xp[i + k], bp2);
                    fma2(acc2[i][3], xp[i + k], bp3);
                }
            }
        }
    }
#pragma unroll
    for (int i = 0; i < 8; i++) {
        float* dst = &g_res[(size_t)(r0 + ty * 8 + i) * D_ + n0 + tx * 8];
        float v[8];
#pragma unroll
        for (int j2 = 0; j2 < 4; j2++) unpack2(acc2[i][j2], v[2 * j2], v[2 * j2 + 1]);
#pragma unroll
        for (int j = 0; j < 8; j++) dst[j] = v[j] + fbs[tx * 8 + j];
    }
}

// ---------------------------------------------------------------------------
// K3: one residual-VQ step (quantizer q), fully fused:
//     scores GEMM (f32x2, double-buffered smem, 1 sync/K-step) -> running
//     argmin -> index write -> residual/qout update -> loss block partial.
//     Block = 128 rows x (1024 codes in chunks of 128). grid = (NBLK, G).
// ---------------------------------------------------------------------------
__global__ __launch_bounds__(256, 2)
void k_vq(const float* __restrict__ cbks, float* __restrict__ out, int q) {
    __shared__ float Rs[2][8][132];
    __shared__ float Cs[2][8][132];
    __shared__ float c2s[128];
    __shared__ float redv[128][17];
    __shared__ int   redi[128][17];
    __shared__ int   bidx[128];
    __shared__ float lred[256];

    const int g   = blockIdx.y;
    const int r0  = blockIdx.x * 128;
    const int tid = threadIdx.x;
    const int tx  = tid & 15, ty = tid >> 4;
    const int goff = g * DG_;
    const float* cb  = cbks + (size_t)(q * G_ + g) * C_ * DG_;
    const float* c2p = g_c2 + (q * G_ + g) * C_;

    float minv[8];
    int   mini[8];
#pragma unroll
    for (int i = 0; i < 8; i++) { minv[i] = 3.4e38f; mini[i] = 0; }

    const int ml = tid >> 1;          // 0..127
    const int kh = (tid & 1) << 2;    // 0 or 4
    const float* resrow = &g_res[(size_t)(r0 + ml) * D_ + goff + kh];

#pragma unroll 1
    for (int cc0 = 0; cc0 < C_; cc0 += 128) {
        const float* crow = &cb[(size_t)(cc0 + ml) * DG_ + kh];
        __syncthreads();                       // prev chunk fully consumed
        if (tid < 128) c2s[tid] = c2p[cc0 + tid];
        // prologue: K-step 0 into buffer 0
        {
            const float4 rv = *(const float4*)&resrow[0];
            const float4 cv = *(const float4*)&crow[0];
            Rs[0][kh + 0][ml] = rv.x; Rs[0][kh + 1][ml] = rv.y;
            Rs[0][kh + 2][ml] = rv.z; Rs[0][kh + 3][ml] = rv.w;
            Cs[0][kh + 0][ml] = cv.x; Cs[0][kh + 1][ml] = cv.y;
            Cs[0][kh + 2][ml] = cv.z; Cs[0][kh + 3][ml] = cv.w;
        }
        __syncthreads();

        u64 acc2[8][4];
#pragma unroll
        for (int i = 0; i < 8; i++)
#pragma unroll
            for (int j = 0; j < 4; j++) acc2[i][j] = 0ull;

#pragma unroll 2
        for (int step = 0; step < 32; step++) {
            const int cur = step & 1;
            float4 rv2, cv2;
            if (step < 31) {                    // prefetch next K-slice
                rv2 = *(const float4*)&resrow[(step + 1) * 8];
                cv2 = *(const float4*)&crow[(step + 1) * 8];
            }
#pragma unroll
            for (int kk = 0; kk < 8; kk++) {
                const float4 a0 = *(const float4*)&Rs[cur][kk][ty * 8];
                const float4 a1 = *(const float4*)&Rs[cur][kk][ty * 8 + 4];
                const float4 b0 = *(const float4*)&Cs[cur][kk][tx * 8];
                const float4 b1 = *(const float4*)&Cs[cur][kk][tx * 8 + 4];
                const u64 bp0 = pack2(b0.x, b0.y), bp1 = pack2(b0.z, b0.w);
                const u64 bp2 = pack2(b1.x, b1.y), bp3 = pack2(b1.z, b1.w);
                const float aa[8] = {a0.x, a0.y, a0.z, a0.w, a1.x, a1.y, a1.z, a1.w};
#pragma unroll
                for (int i = 0; i < 8; i++) {
                    const u64 ap = pack2(aa[i], aa[i]);
                    fma2(acc2[i][0], ap, bp0);
                    fma2(acc2[i][1], ap, bp1);
                    fma2(acc2[i][2], ap, bp2);
                    fma2(acc2[i][3], ap, bp3);
                }
            }
            if (step < 31) {
                const int nxt = cur ^ 1;
                Rs[nxt][kh + 0][ml] = rv2.x; Rs[nxt][kh + 1][ml] = rv2.y;
                Rs[nxt][kh + 2][ml] = rv2.z; Rs[nxt][kh + 3][ml] = rv2.w;
                Cs[nxt][kh + 0][ml] = cv2.x; Cs[nxt][kh + 1][ml] = cv2.y;
                Cs[nxt][kh + 2][ml] = cv2.z; Cs[nxt][kh + 3][ml] = cv2.w;
                __syncthreads();
            }
        }
        // scores + running argmin (ascending index order within thread)
#pragma unroll
        for (int j2 = 0; j2 < 4; j2++) {
#pragma unroll
            for (int i = 0; i < 8; i++) {
                float dlo, dhi;
                unpack2(acc2[i][j2], dlo, dhi);
                const int j = j2 * 2;
                const float s0 = c2s[tx * 8 + j]     - 2.f * dlo;
                const float s1 = c2s[tx * 8 + j + 1] - 2.f * dhi;
                const int idx0 = cc0 + tx * 8 + j;
                if (s0 < minv[i]) { minv[i] = s0; mini[i] = idx0; }
                if (s1 < minv[i]) { minv[i] = s1; mini[i] = idx0 + 1; }
            }
        }
    }

    // cross-thread argmin reduce (per row, across 16 tx lanes; first-index ties)
    __syncthreads();
#pragma unroll
    for (int i = 0; i < 8; i++) {
        redv[ty * 8 + i][tx] = minv[i];
        redi[ty * 8 + i][tx] = mini[i];
    }
    __syncthreads();
    if (tid < 128) {
        float bv = redv[tid][0];
        int   bi = redi[tid][0];
#pragma unroll
        for (int t = 1; t < 16; t++) {
            const float v = redv[tid][t];
            const int   w = redi[tid][t];
            if (v < bv || (v == bv && w < bi)) { bv = v; bi = w; }
        }
        bidx[tid] = bi;
        const int row = r0 + tid;
        const int bb = row / L_;
        const int ll = row - bb * L_;
        out[IDX_OFF + (size_t)(((g * B_ + bb) * L_) + ll) * Q_ + q] = (float)bi;
    }
    __syncthreads();

    // residual -= code ; qout += code (q==0 writes fresh) ; loss partial
    float ls = 0.f;
    {
        const int m    = tid >> 1;
        const int half = (tid & 1) * (DG_ / 2);
        const size_t base = (size_t)(r0 + m) * D_ + goff + half;
        const float* qrow = cb + (size_t)bidx[m] * DG_ + half;
#pragma unroll 4
        for (int dd = 0; dd < DG_ / 2; dd += 4) {
            const float4 cvl = *(const float4*)&qrow[dd];
            float4 rvl = *(float4*)&g_res[base + dd];
            float4 qvl;
            if (q != 0) qvl = *(float4*)&g_qout[base + dd];
            else        qvl = make_float4(0.f, 0.f, 0.f, 0.f);
            rvl.x -= cvl.x; rvl.y -= cvl.y; rvl.z -= cvl.z; rvl.w -= cvl.w;
            qvl.x += cvl.x; qvl.y += cvl.y; qvl.z += cvl.z; qvl.w += cvl.w;
            *(float4*)&g_res[base + dd]  = rvl;
            *(float4*)&g_qout[base + dd] = qvl;
            ls = fmaf(rvl.x, rvl.x, ls); ls = fmaf(rvl.y, rvl.y, ls);
            ls = fmaf(rvl.z, rvl.z, ls); ls = fmaf(rvl.w, rvl.w, ls);
        }
    }
    lred[tid] = ls;
    __syncthreads();
#pragma unroll
    for (int s = 128; s; s >>= 1) {
        if (tid < s) lred[tid] += lred[tid + s];
        __syncthreads();
    }
    if (tid == 0) g_lpart[(q * G_ + g) * NBLK + blockIdx.x] = lred[0];
}

// ---------------------------------------------------------------------------
// K4: post linear + [b,d,l] transpose.  Out[d][l] = sum_e pw[d][e]*qout[l][e]+pb[d]
// f32x2 mainloop; tile rows = d, cols = (b,l) rows -> coalesced transposed stores.
// ---------------------------------------------------------------------------
__global__ __launch_bounds__(256, 2)
void k_post(const float* __restrict__ pw, const float* __restrict__ pb,
            float* __restrict__ out) {
    __shared__ float As[8][132];   // [kk][d]
    __shared__ float Bs[8][132];   // [kk][row]
    const int r0 = blockIdx.x * 128;
    const int d0 = blockIdx.y * 128;
    const int tid = threadIdx.x;
    const int tx = tid & 15, ty = tid >> 4;
    const int ml = tid >> 1;
    const int kh = (tid & 1) << 2;

    u64 acc2[8][4];
#pragma unroll
    for (int i = 0; i < 8; i++)
#pragma unroll
        for (int j = 0; j < 4; j++) acc2[i][j] = 0ull;

#pragma unroll 1
    for (int e0 = 0; e0 < D_; e0 += 8) {
        const float4 av = *(const float4*)&pw[(size_t)(d0 + ml) * D_ + e0 + kh];
        const float4 bv = *(const float4*)&g_qout[(size_t)(r0 + ml) * D_ + e0 + kh];
        __syncthreads();
        As[kh + 0][ml] = av.x; As[kh + 1][ml] = av.y;
        As[kh + 2][ml] = av.z; As[kh + 3][ml] = av.w;
        Bs[kh + 0][ml] = bv.x; Bs[kh + 1][ml] = bv.y;
        Bs[kh + 2][ml] = bv.z; Bs[kh + 3][ml] = bv.w;
        __syncthreads();
#pragma unroll
        for (int kk = 0; kk < 8; kk++) {
            const float4 a0 = *(const float4*)&As[kk][ty * 8];
            const float4 a1 = *(const float4*)&As[kk][ty * 8 + 4];
            const float4 b0 = *(const float4*)&Bs[kk][tx * 8];
            const float4 b1 = *(const float4*)&Bs[kk][tx * 8 + 4];
            const u64 bp0 = pack2(b0.x, b0.y), bp1 = pack2(b0.z, b0.w);
            const u64 bp2 = pack2(b1.x, b1.y), bp3 = pack2(b1.z, b1.w);
            const float aa[8] = {a0.x, a0.y, a0.z, a0.w, a1.x, a1.y, a1.z, a1.w};
#pragma unroll
            for (int i = 0; i < 8; i++) {
                const u64 ap = pack2(aa[i], aa[i]);
                fma2(acc2[i][0], ap, bp0);
                fma2(acc2[i][1], ap, bp1);
                fma2(acc2[i][2], ap, bp2);
                fma2(acc2[i][3], ap, bp3);
            }
        }
    }
    const int b  = r0 / L_;
    const int l0 = r0 - b * L_;
#pragma unroll
    for (int i = 0; i < 8; i++) {
        const int d = d0 + ty * 8 + i;
        const float bias = pb[d];
        float v[8];
#pragma unroll
        for (int j2 = 0; j2 < 4; j2++) unpack2(acc2[i][j2], v[2 * j2], v[2 * j2 + 1]);
        float* dst = &out[(size_t)b * D_ * L_ + (size_t)d * L_ + l0 + tx * 8];
        float4 v0, v1;
        v0.x = v[0] + bias; v0.y = v[1] + bias; v0.z = v[2] + bias; v0.w = v[3] + bias;
        v1.x = v[4] + bias; v1.y = v[5] + bias; v1.z = v[6] + bias; v1.w = v[7] + bias;
        *(float4*)&dst[0] = v0;
        *(float4*)&dst[4] = v1;
    }
}

// K5: deterministic loss finalize.  losses[g][q] = sum(partials) / (B*L*DG)
__global__ void k_loss(float* __restrict__ out) {
    const int t = threadIdx.x;
    if (t < G_ * Q_) {
        const int g = t / Q_, q = t - g * Q_;
        const float* p = &g_lpart[(q * G_ + g) * NBLK];
        float s = 0.f;
        for (int b = 0; b < NBLK; b++) s += p[b];
        out[LOSS_OFF + g * Q_ + q] = s / (float)((long long)B_ * L_ * DG_);
    }
}

// ---------------------------------------------------------------------------
// Launch
// ---------------------------------------------------------------------------
extern "C" void kernel_launch(void* const* d_in, const int* in_sizes, int n_in,
                              void* d_out, int out_size) {
    (void)in_sizes; (void)n_in; (void)out_size;
    const float* x     = (const float*)d_in[0];
    const float* cew   = (const float*)d_in[1];
    const float* ceb   = (const float*)d_in[2];
    const float* pre_w = (const float*)d_in[3];
    const float* pre_b = (const float*)d_in[4];
    const float* cbk   = (const float*)d_in[5];
    const float* pow_  = (const float*)d_in[6];
    const float* pob   = (const float*)d_in[7];
    // d_in[8], d_in[9] = conv_dec_* : the reference discards the decoder conv.
    float* out = (float*)d_out;

    k_fuse<<<dim3(12, 4), 256>>>(cew, pre_w);
    k_fb<<<2, 256>>>(pre_w, ceb, pre_b);
    k_c2<<<(Q_ * G_ * C_ * 32 + 255) / 256, 256>>>(cbk);
    k_conv<<<dim3(NBLK, 4), 256>>>(x);
    for (int q = 0; q < Q_; q++)
        k_vq<<<dim3(NBLK, G_), 256>>>(cbk, out, q);
    k_post<<<dim3(NBLK, 4), 256>>>(pow_, pob, out);
    k_loss<<<1, 32>>>(out);
}